// round 17
// baseline (speedup 1.0000x reference)
#include <cuda_runtime.h>
#include <cuda_bf16.h>
#include <cstdint>
#include <math.h>

#define TT 8192
#define DD 2048
#define NE 8
#define FF 1408
#define KC 32              /* k-chunk in fp32 columns = 32 smem words (16 hi + 16 lo bf16x2) */
#define SRB 40             /* smem row stride (words); %32==8 -> LDS.64 conflict-free */
#define THREADS 128
#define MAX_ASSIGN 17408   /* 136 * 128 */
#define MT 136
/* stage spans (words): gateup A 128*40 | BG 64*40 | BU 64*40 ; down A 128*40 | B 128*40 */
#define GU_SPAN 10240
#define OFF_BG 5120
#define OFF_BU 7680
#define DN_SPAN 10240
#define OFF_B  5120
#define DYN_BYTES (2*DN_SPAN*4)   /* 81920 */
#define WELEM (NE*FF*DD)

// ---------------- scratch (device globals only; no allocation) ----------------
__device__ int   g_tk_idx[TT*2];
__device__ float g_tk_w[TT*2];
__device__ int   g_offs[NE+1];
__device__ int   g_tok[MAX_ASSIGN];
__device__ int   g_slot[TT*2];
__device__ uint32_t g_xt[(size_t)TT*DD];        // x split-bf16, pair-permuted
__device__ uint32_t g_wgt[WELEM];               // wg split-bf16
__device__ uint32_t g_wut[WELEM];               // wu split-bf16
__device__ uint32_t g_wdt[WELEM];               // wd split-bf16
__device__ uint32_t g_act[(size_t)MAX_ASSIGN * FF];  // silu(h)*u split-bf16
__device__ float g_y[(size_t)MAX_ASSIGN * DD];       // per-assignment down output

// ---------------- helpers ----------------
__device__ __forceinline__ uint32_t pack_bf2(float a, float b){
    __nv_bfloat162 t;
    t.x = __float2bfloat16_rn(a);
    t.y = __float2bfloat16_rn(b);
    return *reinterpret_cast<uint32_t*>(&t);
}
__device__ __forceinline__ float bfres(float a){
    return a - __bfloat162float(__float2bfloat16_rn(a));
}
__device__ __forceinline__ void mma_bf16(float c[4],
        uint32_t a0, uint32_t a1, uint32_t a2, uint32_t a3,
        uint32_t b0, uint32_t b1){
    asm volatile(
        "mma.sync.aligned.m16n8k16.row.col.f32.bf16.bf16.f32 "
        "{%0,%1,%2,%3}, {%4,%5,%6,%7}, {%8,%9}, {%0,%1,%2,%3};\n"
        : "+f"(c[0]), "+f"(c[1]), "+f"(c[2]), "+f"(c[3])
        : "r"(a0), "r"(a1), "r"(a2), "r"(a3), "r"(b0), "r"(b1));
}
__device__ __forceinline__ uint32_t smem_u32(const void* p){
    uint32_t a; asm("{ .reg .u64 t; cvta.to.shared.u64 t, %1; cvt.u32.u64 %0, t; }" : "=r"(a) : "l"(p)); return a;
}
__device__ __forceinline__ void cp16(uint32_t dst, const void* src){
    asm volatile("cp.async.cg.shared.global [%0], [%1], 16;" :: "r"(dst), "l"(src));
}
__device__ __forceinline__ void cp16z(uint32_t dst, const void* src){
    asm volatile("cp.async.cg.shared.global [%0], [%1], 16, 0;" :: "r"(dst), "l"(src));
}
#define CP_COMMIT() asm volatile("cp.async.commit_group;" ::: "memory")
#define CP_WAIT0()  asm volatile("cp.async.wait_group 0;" ::: "memory")

// split a 32-fp32 chunk -> [16 hi words | 16 lo words], each 8-group pair-permuted
__device__ __forceinline__ void split32(const float4* __restrict__ src, uint4* __restrict__ dst){
    float f[32];
#pragma unroll
    for (int t = 0; t < 8; t++){
        float4 v = src[t];
        f[4*t]=v.x; f[4*t+1]=v.y; f[4*t+2]=v.z; f[4*t+3]=v.w;
    }
    uint32_t hw[16], lw[16];
#pragma unroll
    for (int t = 0; t < 16; t++){
        float a = f[2*t], b = f[2*t+1];
        hw[t] = pack_bf2(a, b);
        lw[t] = pack_bf2(bfres(a), bfres(b));
    }
    uint32_t o[32];
#pragma unroll
    for (int gi = 0; gi < 2; gi++)
#pragma unroll
        for (int t = 0; t < 4; t++){
            o[gi*8 + 2*t]      = hw[gi*8 + t];
            o[gi*8 + 2*t + 1]  = hw[gi*8 + t + 4];
            o[16 + gi*8 + 2*t]     = lw[gi*8 + t];
            o[16 + gi*8 + 2*t + 1] = lw[gi*8 + t + 4];
        }
#pragma unroll
    for (int t = 0; t < 8; t++)
        dst[t] = make_uint4(o[4*t], o[4*t+1], o[4*t+2], o[4*t+3]);
}

// ---------------- weight pre-convert ----------------
__global__ void conv_kernel(const float4* __restrict__ wg,
                            const float4* __restrict__ wu,
                            const float4* __restrict__ wd){
    size_t i = (size_t)blockIdx.x * blockDim.x + threadIdx.x;   // one 32-float chunk
    if (i >= WELEM/32) return;
    split32(wg + i*8, reinterpret_cast<uint4*>(g_wgt) + i*8);
    split32(wu + i*8, reinterpret_cast<uint4*>(g_wut) + i*8);
    split32(wd + i*8, reinterpret_cast<uint4*>(g_wdt) + i*8);
}
__global__ void xconv_kernel(const float4* __restrict__ x){
    size_t i = (size_t)blockIdx.x * blockDim.x + threadIdx.x;
    if (i >= (size_t)TT*DD/32) return;
    split32(x + i*8, reinterpret_cast<uint4*>(g_xt) + i*8);
}

// ---------------- router: logits, top-2, renormalized weights ----------------
__global__ void router_kernel(const float* __restrict__ x,
                              const float* __restrict__ gw,
                              float* __restrict__ logits){
    int warp = (blockIdx.x * blockDim.x + threadIdx.x) >> 5;
    int lane = threadIdx.x & 31;
    if (warp >= TT) return;
    const float* xr = x + (size_t)warp * DD;
    float acc[NE];
#pragma unroll
    for (int e = 0; e < NE; e++) acc[e] = 0.f;
    for (int c = lane * 4; c < DD; c += 128){
        float4 xv = *reinterpret_cast<const float4*>(xr + c);
#pragma unroll
        for (int e = 0; e < NE; e++){
            float4 gv = *reinterpret_cast<const float4*>(gw + e*DD + c);
            acc[e] += xv.x*gv.x; acc[e] += xv.y*gv.y;
            acc[e] += xv.z*gv.z; acc[e] += xv.w*gv.w;
        }
    }
#pragma unroll
    for (int e = 0; e < NE; e++){
#pragma unroll
        for (int o = 16; o > 0; o >>= 1) acc[e] += __shfl_xor_sync(0xffffffffu, acc[e], o);
    }
    if (lane == 0){
#pragma unroll
        for (int e = 0; e < NE; e++) logits[(size_t)warp*NE + e] = acc[e];
        int i0 = 0; float l0 = acc[0];
#pragma unroll
        for (int e = 1; e < NE; e++) if (acc[e] > l0){ l0 = acc[e]; i0 = e; }
        int i1 = -1; float l1 = -1e30f;
#pragma unroll
        for (int e = 0; e < NE; e++) if (e != i0 && acc[e] > l1){ l1 = acc[e]; i1 = e; }
        float q  = expf(l1 - l0);
        float w0 = 1.f / (1.f + q);
        float w1 = q  / (1.f + q);
        g_tk_idx[warp*2+0] = i0; g_tk_idx[warp*2+1] = i1;
        g_tk_w [warp*2+0] = w0; g_tk_w [warp*2+1] = w1;
    }
}

// ---------------- build per-expert token lists (128-aligned segments) ----------------
__global__ void build_kernel(){
    __shared__ int cnt[NE];
    __shared__ int offs[NE+1];
    __shared__ int cur[NE];
    int tid = threadIdx.x;
    if (tid < NE) cnt[tid] = 0;
    __syncthreads();
    for (int i = tid; i < TT*2; i += blockDim.x) atomicAdd(&cnt[g_tk_idx[i]], 1);
    __syncthreads();
    if (tid == 0){
        int o = 0;
        for (int e = 0; e < NE; e++){ offs[e] = o; cur[e] = o; o += (cnt[e] + 127) & ~127; }
        offs[NE] = o;
        for (int e = 0; e <= NE; e++) g_offs[e] = offs[e];
    }
    __syncthreads();
    for (int i = tid; i < MAX_ASSIGN; i += blockDim.x) g_tok[i] = -1;
    __syncthreads();
    for (int i = tid; i < TT*2; i += blockDim.x){
        int e = g_tk_idx[i];
        int slot = atomicAdd(&cur[e], 1);
        g_tok[slot] = i >> 1;
        g_slot[i] = slot;
    }
}

// ---------------- GEMM 1: gathered x @ {w_gate,w_up}^T -> act = silu(h)*u ----------------
// Block 128 rows x 64 F; 4 warps; warp tile 64x32 x BOTH h,u. Split-bf16 3-term MMA.
__global__ __launch_bounds__(THREADS) void gateup_kernel(){
    extern __shared__ uint32_t dyn[];
    __shared__ int sTok[128];

    int fb   = blockIdx.x * 64;
    int row0 = blockIdx.y * 128;
    int tid  = threadIdx.x;

    if (row0 >= g_offs[NE]) return;

    int e = 0;
#pragma unroll
    for (int i = 0; i < NE-1; i++) if (row0 >= g_offs[i+1]) e = i + 1;

    sTok[tid] = g_tok[row0 + tid];
    __syncthreads();

    int warp = tid >> 5, lane = tid & 31;
    int g = lane >> 2, tg = lane & 3;
    int tg2 = tg << 1;
    int wm = warp & 1, wn = warp >> 1;

    int rL = tid >> 3;            // 0..15
    int cL = (tid & 7) << 2;      // 0,4,...,28
    uint32_t sb = smem_u32(dyn);

    const uint32_t* aSrc[8];
#pragma unroll
    for (int i = 0; i < 8; i++){
        int tok = sTok[rL + 16*i];
        aSrc[i] = (tok >= 0) ? (g_xt + (size_t)tok * DD + cL) : (const uint32_t*)0;
    }
    const uint32_t* gSrc = g_wgt + (size_t)(e*FF + fb + rL) * DD + cL;
    const uint32_t* uSrc = g_wut + (size_t)(e*FF + fb + rL) * DD + cL;

    uint32_t dA[8], dG[4], dU[4];
#pragma unroll
    for (int i = 0; i < 8; i++) dA[i] = ((rL + 16*i)*SRB + cL) * 4;
#pragma unroll
    for (int i = 0; i < 4; i++){
        dG[i] = (OFF_BG + (rL + 16*i)*SRB + cL) * 4;
        dU[i] = (OFF_BU + (rL + 16*i)*SRB + cL) * 4;
    }

    float hC[4][4][4], uC[4][4][4];
#pragma unroll
    for (int mi = 0; mi < 4; mi++)
#pragma unroll
        for (int ni = 0; ni < 4; ni++)
#pragma unroll
            for (int j = 0; j < 4; j++){ hC[mi][ni][j] = 0.f; uC[mi][ni][j] = 0.f; }

    const int NCH = DD / KC;   // 64
#define GU_LOAD(ck, st) do {                                              \
        uint32_t base = sb + (uint32_t)(st)*GU_SPAN*4;                    \
        int koff = (ck) * KC;                                             \
        _Pragma("unroll")                                                 \
        for (int i = 0; i < 8; i++){                                      \
            if (aSrc[i]) cp16(base + dA[i], aSrc[i] + koff);              \
            else         cp16z(base + dA[i], g_xt);                       \
        }                                                                 \
        _Pragma("unroll")                                                 \
        for (int i = 0; i < 4; i++){                                      \
            cp16(base + dG[i], gSrc + (size_t)(16*i)*DD + koff);          \
            cp16(base + dU[i], uSrc + (size_t)(16*i)*DD + koff);         \
        }                                                                 \
    } while(0)

    GU_LOAD(0, 0); CP_COMMIT();

    for (int ck = 0; ck < NCH; ck++){
        CP_WAIT0();
        __syncthreads();
        if (ck + 1 < NCH){ GU_LOAD(ck + 1, (ck + 1) & 1); CP_COMMIT(); }
        int cb = (ck & 1) * GU_SPAN;
#pragma unroll
        for (int s = 0; s < 2; s++){
            uint32_t ah[4][4], al[4][4];
#pragma unroll
            for (int mi = 0; mi < 4; mi++){
                int r0 = (wm*64 + mi*16 + g)*SRB + cb + 8*s + tg2;
                uint2 h0 = *reinterpret_cast<const uint2*>(&dyn[r0]);
                uint2 h1 = *reinterpret_cast<const uint2*>(&dyn[r0 + 8*SRB]);
                uint2 l0 = *reinterpret_cast<const uint2*>(&dyn[r0 + 16]);
                uint2 l1 = *reinterpret_cast<const uint2*>(&dyn[r0 + 8*SRB + 16]);
                ah[mi][0]=h0.x; ah[mi][2]=h0.y; ah[mi][1]=h1.x; ah[mi][3]=h1.y;
                al[mi][0]=l0.x; al[mi][2]=l0.y; al[mi][1]=l1.x; al[mi][3]=l1.y;
            }
#pragma unroll
            for (int ni = 0; ni < 4; ni++){
                int br = (wn*32 + ni*8 + g)*SRB + cb + 8*s + tg2;
                uint2 gh = *reinterpret_cast<const uint2*>(&dyn[OFF_BG + br]);
                uint2 gl = *reinterpret_cast<const uint2*>(&dyn[OFF_BG + br + 16]);
                uint2 uh = *reinterpret_cast<const uint2*>(&dyn[OFF_BU + br]);
                uint2 ul = *reinterpret_cast<const uint2*>(&dyn[OFF_BU + br + 16]);
#pragma unroll
                for (int mi = 0; mi < 4; mi++){
                    mma_bf16(hC[mi][ni], ah[mi][0],ah[mi][1],ah[mi][2],ah[mi][3], gh.x, gh.y);
                    mma_bf16(hC[mi][ni], ah[mi][0],ah[mi][1],ah[mi][2],ah[mi][3], gl.x, gl.y);
                    mma_bf16(hC[mi][ni], al[mi][0],al[mi][1],al[mi][2],al[mi][3], gh.x, gh.y);
                    mma_bf16(uC[mi][ni], ah[mi][0],ah[mi][1],ah[mi][2],ah[mi][3], uh.x, uh.y);
                    mma_bf16(uC[mi][ni], ah[mi][0],ah[mi][1],ah[mi][2],ah[mi][3], ul.x, ul.y);
                    mma_bf16(uC[mi][ni], al[mi][0],al[mi][1],al[mi][2],al[mi][3], uh.x, uh.y);
                }
            }
        }
    }
#undef GU_LOAD
    // epilogue: act = silu(h)*u, stored split-bf16 pair-permuted
    {
        int w  = 0; // per-ni computed below
#pragma unroll
        for (int mi = 0; mi < 4; mi++)
#pragma unroll
            for (int ni = 0; ni < 4; ni++){
                w = ni*4 + tg;                       // hi-word index 0..15 in 32-col chunk
                int wi = w & 7, gi = w >> 3;
                int pos = gi*8 + ((wi < 4) ? 2*wi : 2*(wi-4)+1);
#pragma unroll
                for (int half = 0; half < 2; half++){
                    int r = row0 + wm*64 + mi*16 + g + half*8;
                    size_t base = (size_t)r*FF + fb + wn*32;
                    float h0 = hC[mi][ni][half*2+0], h1 = hC[mi][ni][half*2+1];
                    float u0 = uC[mi][ni][half*2+0], u1 = uC[mi][ni][half*2+1];
                    float v0 = h0 / (1.f + expf(-h0)) * u0;
                    float v1 = h1 / (1.f + expf(-h1)) * u1;
                    g_act[base + pos]      = pack_bf2(v0, v1);
                    g_act[base + 16 + pos] = pack_bf2(bfres(v0), bfres(v1));
                }
            }
    }
}

// ---------------- GEMM 2: act @ w_down^T -> y ----------------
// Block 128 rows x 128 D; 4 warps; warp tile 64x64. Split-bf16 3-term MMA.
__global__ __launch_bounds__(THREADS) void down_kernel(){
    extern __shared__ uint32_t dyn[];

    int nb   = blockIdx.x * 128;
    int row0 = blockIdx.y * 128;
    int tid  = threadIdx.x;

    if (row0 >= g_offs[NE]) return;

    int e = 0;
#pragma unroll
    for (int i = 0; i < NE-1; i++) if (row0 >= g_offs[i+1]) e = i + 1;

    int warp = tid >> 5, lane = tid & 31;
    int g = lane >> 2, tg = lane & 3;
    int tg2 = tg << 1;
    int wm = warp & 1, wn = warp >> 1;

    int rL = tid >> 3;
    int cL = (tid & 7) << 2;
    uint32_t sb = smem_u32(dyn);

    const uint32_t* aSrc = g_act + (size_t)(row0 + rL) * FF + cL;
    const uint32_t* bSrc = g_wdt + (size_t)(e*DD + nb + rL) * FF + cL;

    uint32_t dA[8], dB[8];
#pragma unroll
    for (int i = 0; i < 8; i++){
        dA[i] = ((rL + 16*i)*SRB + cL) * 4;
        dB[i] = (OFF_B + (rL + 16*i)*SRB + cL) * 4;
    }

    float C[4][8][4];
#pragma unroll
    for (int mi = 0; mi < 4; mi++)
#pragma unroll
        for (int ni = 0; ni < 8; ni++)
#pragma unroll
            for (int j = 0; j < 4; j++) C[mi][ni][j] = 0.f;

    const int NCH = FF / KC;   // 44
#define DN_LOAD(ck, st) do {                                              \
        uint32_t base = sb + (uint32_t)(st)*DN_SPAN*4;                    \
        int koff = (ck) * KC;                                             \
        _Pragma("unroll")                                                 \
        for (int i = 0; i < 8; i++){                                      \
            cp16(base + dA[i], aSrc + (size_t)(16*i)*FF + koff);          \
            cp16(base + dB[i], bSrc + (size_t)(16*i)*FF + koff);         \
        }                                                                 \
    } while(0)

    DN_LOAD(0, 0); CP_COMMIT();

    for (int ck = 0; ck < NCH; ck++){
        CP_WAIT0();
        __syncthreads();
        if (ck + 1 < NCH){ DN_LOAD(ck + 1, (ck + 1) & 1); CP_COMMIT(); }
        int cb = (ck & 1) * DN_SPAN;
#pragma unroll
        for (int s = 0; s < 2; s++){
            uint32_t ah[4][4], al[4][4];
#pragma unroll
            for (int mi = 0; mi < 4; mi++){
                int r0 = (wm*64 + mi*16 + g)*SRB + cb + 8*s + tg2;
                uint2 h0 = *reinterpret_cast<const uint2*>(&dyn[r0]);
                uint2 h1 = *reinterpret_cast<const uint2*>(&dyn[r0 + 8*SRB]);
                uint2 l0 = *reinterpret_cast<const uint2*>(&dyn[r0 + 16]);
                uint2 l1 = *reinterpret_cast<const uint2*>(&dyn[r0 + 8*SRB + 16]);
                ah[mi][0]=h0.x; ah[mi][2]=h0.y; ah[mi][1]=h1.x; ah[mi][3]=h1.y;
                al[mi][0]=l0.x; al[mi][2]=l0.y; al[mi][1]=l1.x; al[mi][3]=l1.y;
            }
#pragma unroll
            for (int ni = 0; ni < 8; ni++){
                int br = (wn*64 + ni*8 + g)*SRB + cb + 8*s + tg2;
                uint2 bh = *reinterpret_cast<const uint2*>(&dyn[OFF_B + br]);
                uint2 bl = *reinterpret_cast<const uint2*>(&dyn[OFF_B + br + 16]);
#pragma unroll
                for (int mi = 0; mi < 4; mi++){
                    mma_bf16(C[mi][ni], ah[mi][0],ah[mi][1],ah[mi][2],ah[mi][3], bh.x, bh.y);
                    mma_bf16(C[mi][ni], ah[mi][0],ah[mi][1],ah[mi][2],ah[mi][3], bl.x, bl.y);
                    mma_bf16(C[mi][ni], al[mi][0],al[mi][1],al[mi][2],al[mi][3], bh.x, bh.y);
                }
            }
        }
    }
#undef DN_LOAD
    // epilogue: plain STG of per-assignment rows (fp32)
#pragma unroll
    for (int mi = 0; mi < 4; mi++)
#pragma unroll
        for (int half = 0; half < 2; half++){
            int rl = wm*64 + mi*16 + g + half*8;
            float* yrow = g_y + (size_t)(row0 + rl) * DD + nb;
#pragma unroll
            for (int ni = 0; ni < 8; ni++){
                int cb2 = wn*64 + ni*8 + tg*2;
                *reinterpret_cast<float2*>(yrow + cb2) =
                    make_float2(C[mi][ni][half*2+0], C[mi][ni][half*2+1]);
            }
        }
}

// ---------------- combine: out[t] = w0*y[slot0] + w1*y[slot1] (coalesced) ----------------
__global__ void combine_kernel(float* __restrict__ out){
    int gid = blockIdx.x * 256 + threadIdx.x;
    int t = gid >> 9;
    int d = (gid & 511) << 2;
    int s0 = g_slot[2*t], s1 = g_slot[2*t+1];
    float w0 = g_tk_w[2*t], w1 = g_tk_w[2*t+1];
    float4 y0 = *reinterpret_cast<const float4*>(&g_y[(size_t)s0*DD + d]);
    float4 y1 = *reinterpret_cast<const float4*>(&g_y[(size_t)s1*DD + d]);
    float4 r = make_float4(w0*y0.x + w1*y1.x, w0*y0.y + w1*y1.y,
                           w0*y0.z + w1*y1.z, w0*y0.w + w1*y1.w);
    *reinterpret_cast<float4*>(&out[(size_t)t*DD + d]) = r;
}

// ---------------- launch ----------------
extern "C" void kernel_launch(void* const* d_in, const int* in_sizes, int n_in,
                              void* d_out, int out_size){
    const float* x  = (const float*)d_in[0];   // [T, D]
    const float* gw = (const float*)d_in[1];   // [E, D]
    const float* wg = (const float*)d_in[2];   // [E, F, D]
    const float* wu = (const float*)d_in[3];   // [E, F, D]
    const float* wd = (const float*)d_in[4];   // [E, D, F]
    float* out    = (float*)d_out;             // [T*D] final, then [T*E] logits
    float* logits = out + (size_t)TT * DD;

    static int attr_done = 0;
    if (!attr_done){
        cudaFuncSetAttribute(gateup_kernel, cudaFuncAttributeMaxDynamicSharedMemorySize, DYN_BYTES);
        cudaFuncSetAttribute(down_kernel,   cudaFuncAttributeMaxDynamicSharedMemorySize, DYN_BYTES);
        attr_done = 1;
    }

    conv_kernel <<<(WELEM/32 + 255)/256, 256>>>((const float4*)wg, (const float4*)wu, (const float4*)wd);
    xconv_kernel<<<((TT*DD/32) + 255)/256, 256>>>((const float4*)x);
    router_kernel<<<TT/8, 256>>>(x, gw, logits);
    build_kernel<<<1, 1024>>>();
    gateup_kernel<<<dim3(FF/64, MT), THREADS, DYN_BYTES>>>();
    down_kernel  <<<dim3(DD/128, MT), THREADS, DYN_BYTES>>>();
    combine_kernel<<<TT*512/256, 256>>>(out);
}